// round 13
// baseline (speedup 1.0000x reference)
#include <cuda_runtime.h>
#include <cuda_fp16.h>
#include <cstdint>

#define PB 2
#define PH 12
#define PT 2048
#define PD 64
#define PR 16
#define PD_STD 48
#define PBH (PB * PH)
#define QT 64
#define KT 128
#define LOG2E 1.4426950408889634f

// smem byte offsets (attn) — 4 CTA/SM budget
#define SK0 0          // K stage0 128x128B = 16384
#define SK1 16384
#define SV  32768      // V single buffer (also Q staging at startup)
#define SB0 49152      // bias 128 f32
#define SB1 49664
#define SMEM_BYTES 50176

__device__ __half g_Qh[PBH * PT * PD];
__device__ __half g_Kh[PBH * PT * PD];
__device__ __half g_Vh[PBH * PT * PD];
__device__ float  g_bw[PBH * PT];

__device__ __forceinline__ void mma16816(float& d0, float& d1, float& d2, float& d3,
                                         unsigned a0, unsigned a1, unsigned a2, unsigned a3,
                                         unsigned b0, unsigned b1) {
    asm volatile(
        "mma.sync.aligned.m16n8k16.row.col.f32.f16.f16.f32 "
        "{%0,%1,%2,%3},{%4,%5,%6,%7},{%8,%9},{%0,%1,%2,%3};"
        : "+f"(d0), "+f"(d1), "+f"(d2), "+f"(d3)
        : "r"(a0), "r"(a1), "r"(a2), "r"(a3), "r"(b0), "r"(b1));
}
__device__ __forceinline__ void mma16816_init(float& d0, float& d1, float& d2, float& d3,
                                              unsigned a0, unsigned a1, unsigned a2, unsigned a3,
                                              unsigned b0, unsigned b1, float c0, float c1) {
    asm volatile(
        "mma.sync.aligned.m16n8k16.row.col.f32.f16.f16.f32 "
        "{%0,%1,%2,%3},{%4,%5,%6,%7},{%8,%9},{%10,%11,%10,%11};"
        : "=f"(d0), "=f"(d1), "=f"(d2), "=f"(d3)
        : "r"(a0), "r"(a1), "r"(a2), "r"(a3), "r"(b0), "r"(b1),
          "f"(c0), "f"(c1));
}
__device__ __forceinline__ void ldsm4(unsigned& r0, unsigned& r1, unsigned& r2, unsigned& r3,
                                      unsigned addr) {
    asm volatile("ldmatrix.sync.aligned.m8n8.x4.shared.b16 {%0,%1,%2,%3}, [%4];"
                 : "=r"(r0), "=r"(r1), "=r"(r2), "=r"(r3) : "r"(addr));
}
__device__ __forceinline__ void ldsm4t(unsigned& r0, unsigned& r1, unsigned& r2, unsigned& r3,
                                       unsigned addr) {
    asm volatile("ldmatrix.sync.aligned.m8n8.x4.trans.shared.b16 {%0,%1,%2,%3}, [%4];"
                 : "=r"(r0), "=r"(r1), "=r"(r2), "=r"(r3) : "r"(addr));
}
__device__ __forceinline__ void cpa16(unsigned dst, const void* src) {
    asm volatile("cp.async.cg.shared.global [%0], [%1], 16;" :: "r"(dst), "l"(src));
}
__device__ __forceinline__ float ex2(float x) {
    float y; asm("ex2.approx.ftz.f32 %0, %1;" : "=f"(y) : "f"(x)); return y;
}
// packed fp16 exp2 on a half2 register
__device__ __forceinline__ unsigned ex2h(__half2 x) {
    unsigned y;
    asm("ex2.approx.f16x2 %0, %1;" : "=r"(y) : "r"(*reinterpret_cast<const unsigned*>(&x)));
    return y;
}
__device__ __forceinline__ __half2 u2h(unsigned u) {
    return *reinterpret_cast<const __half2*>(&u);
}

// ---------------------------------------------------------------------------
// Fused prologue (R12, unchanged): fp16 staging + HFMA2 low-rank projection.
// ---------------------------------------------------------------------------
#define QPH 68
#define WPH 66
__global__ __launch_bounds__(256) void aug_kernel(
    const float* __restrict__ Q, const float* __restrict__ K,
    const float* __restrict__ V, const float* __restrict__ d_bias,
    const float* __restrict__ W,
    const float* __restrict__ w_std, const float* __restrict__ w_rec,
    const float* __restrict__ w_disc)
{
    __shared__ __half sWh[PR * WPH];
    __shared__ __half sQh[64 * QPH];
    __shared__ __half sKh[64 * QPH];
    __shared__ float sLQ[64 * 16];
    __shared__ float sLK[64 * 16];

    const int tid = threadIdx.x;
    const int bh  = blockIdx.y;
    const int h   = bh % PH;
    const int t0  = blockIdx.x * 64;
    const size_t gbase = ((size_t)bh * PT + t0) * PD;

    for (int idx = tid; idx < PD * PR; idx += 256) {
        const int rj = idx & 15, j = idx >> 4;
        sWh[rj * WPH + j] = __float2half_rn(W[j * PR + rj]);
    }
#pragma unroll
    for (int k = 0; k < 4; k++) {
        const int i = tid + k * 256;
        const int r = i >> 4, c4 = (i & 15) * 4;
        const float4 qv = reinterpret_cast<const float4*>(Q + gbase)[i];
        const float4 kv = reinterpret_cast<const float4*>(K + gbase)[i];
        __half2 qh[2] = {__floats2half2_rn(qv.x, qv.y), __floats2half2_rn(qv.z, qv.w)};
        __half2 kh[2] = {__floats2half2_rn(kv.x, kv.y), __floats2half2_rn(kv.z, kv.w)};
        *reinterpret_cast<uint2*>(&sQh[r * QPH + c4]) = *reinterpret_cast<uint2*>(qh);
        *reinterpret_cast<uint2*>(&sKh[r * QPH + c4]) = *reinterpret_cast<uint2*>(kh);
    }
    __syncthreads();

    {
        const int r = tid >> 2, c4 = (tid & 3) * 4;
        __half2 aq[4], ak[4];
#pragma unroll
        for (int u = 0; u < 4; u++) { aq[u] = __half2(0, 0); ak[u] = __half2(0, 0); }
#pragma unroll
        for (int jp = 0; jp < 32; jp++) {
            const __half2 q2 = *reinterpret_cast<const __half2*>(&sQh[r * QPH + 2 * jp]);
            const __half2 k2 = *reinterpret_cast<const __half2*>(&sKh[r * QPH + 2 * jp]);
#pragma unroll
            for (int u = 0; u < 4; u++) {
                const __half2 w2 =
                    *reinterpret_cast<const __half2*>(&sWh[(c4 + u) * WPH + 2 * jp]);
                aq[u] = __hfma2(q2, w2, aq[u]);
                ak[u] = __hfma2(k2, w2, ak[u]);
            }
        }
#pragma unroll
        for (int u = 0; u < 4; u++) {
            sLQ[r * 16 + c4 + u] = __low2float(aq[u]) + __high2float(aq[u]);
            sLK[r * 16 + c4 + u] = __low2float(ak[u]) + __high2float(ak[u]);
        }
    }
    __syncthreads();

    {
        const float sstd = sqrtf(w_std[h]);
        const float srec = sqrtf(w_rec[h]);
        const float SCL = 0.125f * LOG2E;
        const int r = tid >> 2, d0 = (tid & 3) * 16;
        const size_t grow = gbase + (size_t)r * PD + d0;

        __half2 qo[8], ko[8], vo[8];
#pragma unroll
        for (int j = 0; j < 8; j++) {
            const int d = d0 + 2 * j;
            float q0, q1, k0, k1;
            if (d < PD_STD) {
                const __half2 qh = *reinterpret_cast<const __half2*>(&sQh[r * QPH + d]);
                const __half2 kh = *reinterpret_cast<const __half2*>(&sKh[r * QPH + d]);
                q0 = SCL * sstd * __low2float(qh);  q1 = SCL * sstd * __high2float(qh);
                k0 = sstd * __low2float(kh);        k1 = sstd * __high2float(kh);
            } else {
                const int rr = d - PD_STD;
                q0 = SCL * srec * sLK[r * 16 + rr]; q1 = SCL * srec * sLK[r * 16 + rr + 1];
                k0 = srec * sLQ[r * 16 + rr];       k1 = srec * sLQ[r * 16 + rr + 1];
            }
            qo[j] = __floats2half2_rn(q0, q1);
            ko[j] = __floats2half2_rn(k0, k1);
        }
#pragma unroll
        for (int j4 = 0; j4 < 4; j4++) {
            const float4 vv = *reinterpret_cast<const float4*>(&V[grow + 4 * j4]);
            vo[2 * j4]     = __floats2half2_rn(vv.x, vv.y);
            vo[2 * j4 + 1] = __floats2half2_rn(vv.z, vv.w);
        }
        *reinterpret_cast<uint4*>(&g_Qh[grow])     = *reinterpret_cast<uint4*>(&qo[0]);
        *reinterpret_cast<uint4*>(&g_Qh[grow + 8]) = *reinterpret_cast<uint4*>(&qo[4]);
        *reinterpret_cast<uint4*>(&g_Kh[grow])     = *reinterpret_cast<uint4*>(&ko[0]);
        *reinterpret_cast<uint4*>(&g_Kh[grow + 8]) = *reinterpret_cast<uint4*>(&ko[4]);
        *reinterpret_cast<uint4*>(&g_Vh[grow])     = *reinterpret_cast<uint4*>(&vo[0]);
        *reinterpret_cast<uint4*>(&g_Vh[grow + 8]) = *reinterpret_cast<uint4*>(&vo[4]);
        if (tid < 64)
            g_bw[(size_t)bh * PT + t0 + tid] =
                LOG2E * w_disc[h] * d_bias[(size_t)bh * PT + t0 + tid];
    }
}

// ---------------------------------------------------------------------------
// Loaders: K (+bias) double-buffered; V single-buffered. Separate groups.
// ---------------------------------------------------------------------------
__device__ __forceinline__ void load_K(unsigned sb, int stage, const __half* Kt,
                                       const float* bt, int tid, int nch)
{
    const unsigned kb = sb + (stage ? SK1 : SK0);
    const unsigned bb = sb + (stage ? SB1 : SB0);
#pragma unroll
    for (int i = 0; i < 8; i++) {
        if (i < nch) {
            const int ch = tid + i * 128;
            const int r = ch >> 3, a = ch & 7;
            cpa16(kb + (unsigned)(r * 128 + ((a ^ (r & 7)) << 4)), Kt + r * 64 + a * 8);
        }
    }
    if (tid < 32) cpa16(bb + (unsigned)tid * 16u, bt + tid * 4);
    asm volatile("cp.async.commit_group;");
}
__device__ __forceinline__ void load_V(unsigned sb, const __half* Vt, int tid, int nch)
{
    const unsigned vb = sb + SV;
#pragma unroll
    for (int i = 0; i < 8; i++) {
        if (i < nch) {
            const int ch = tid + i * 128;
            const int r = ch >> 3, a = ch & 7;
            cpa16(vb + (unsigned)(r * 128 + ((a ^ (r & 7)) << 4)), Vt + r * 64 + a * 8);
        }
    }
    asm volatile("cp.async.commit_group;");
}

// ---------------------------------------------------------------------------
// Flash attention: 4 CTA/SM. S packed to fp16 after per-A2-pair QK; softmax
// in packed fp16 (HSUB2 + ex2.f16x2); V single-buffered; bias in mma C;
// ones-column row sums; half-tile final epilogue.
// ---------------------------------------------------------------------------
__global__ __launch_bounds__(128, 4) void attn_kernel(float* __restrict__ out)
{
    extern __shared__ char sm[];
    const unsigned sb = (unsigned)__cvta_generic_to_shared(sm);

    const int bh = blockIdx.y;
    const int q_tile = (PT / QT - 1) - blockIdx.x;
    const int nkt = q_tile / 2 + 1;
    const int lastnch = (q_tile & 1) ? 8 : 4;
    const size_t base = (size_t)bh * PT * PD;
    const __half* Kg = g_Kh + base;
    const __half* Vg = g_Vh + base;
    const float*  bg = g_bw + (size_t)bh * PT;

    const int tid = threadIdx.x;
    const int w = tid >> 5, lane = tid & 31;
    const int g = lane >> 2, c = lane & 3;

    const int kr  = 8 * (lane >> 4) + (lane & 7);
    const int kao = (lane >> 3) & 1;
    const int qr  = 16 * w + 8 * ((lane >> 3) & 1) + (lane & 7);
    const int qao = lane >> 4;
    const int vro = 8 * ((lane >> 3) & 1) + (lane & 7);
    const int vao = lane >> 4;
    const int qsw = qr & 7, ksw = kr & 7, vsw = vro & 7;
    const int grow0 = q_tile * QT + 16 * w + g;

    unsigned colK[4], colV[4];
#pragma unroll
    for (int kk = 0; kk < 4; kk++) {
        colK[kk] = (unsigned)(((2 * kk + kao) ^ ksw) << 4);
        colV[kk] = (unsigned)(((2 * kk + vao) ^ vsw) << 4);
    }
    const unsigned vb2 = sb + SV + (unsigned)vro * 128u;   // V fixed buffer

    // ---- startup: stage Q through the V buffer, lift to registers ----
    {
        const __half* Qt = g_Qh + base + (size_t)q_tile * QT * PD;
#pragma unroll
        for (int i = 0; i < 4; i++) {
            const int ch = tid + i * 128;
            const int r = ch >> 3, a = ch & 7;
            cpa16(sb + SV + (unsigned)(r * 128 + ((a ^ (r & 7)) << 4)), Qt + r * 64 + a * 8);
        }
        asm volatile("cp.async.commit_group;");
        asm volatile("cp.async.wait_group 0;");
    }
    __syncthreads();
    unsigned qf[4][4];
    {
        const unsigned qbase2 = sb + SV + (unsigned)qr * 128u;
#pragma unroll
        for (int kk = 0; kk < 4; kk++)
            ldsm4(qf[kk][0], qf[kk][1], qf[kk][2], qf[kk][3],
                  qbase2 + (unsigned)(((2 * kk + qao) ^ qsw) << 4));
    }
    __syncthreads();   // all warps done reading Q before V(0) overwrites

    load_K(sb, 0, Kg, bg, tid, (nkt == 1) ? lastnch : 8);
    load_V(sb, Vg, tid, (nkt == 1) ? lastnch : 8);

    float acc[8][4];
#pragma unroll
    for (int nb = 0; nb < 8; nb++)
#pragma unroll
        for (int j = 0; j < 4; j++) acc[nb][j] = 0.f;
    float accl[4] = {0.f, 0.f, 0.f, 0.f};
    float m0 = -1e30f, m1 = -1e30f;

    int stage = 0;
    // ======================= main loop: full, unmasked tiles ================
    for (int kt = 0; kt < nkt - 1; kt++) {
        asm volatile("cp.async.wait_group 1;");   // K(kt) ready
        __syncthreads();
        load_K(sb, stage ^ 1, Kg + (size_t)(kt + 1) * KT * PD, bg + (kt + 1) * KT,
               tid, (kt + 2 == nkt) ? lastnch : 8);

        const unsigned kb2 = sb + (stage ? SK1 : SK0) + (unsigned)kr * 128u;
        const float* sBb = (const float*)(sm + (stage ? SB1 : SB0));

        // ---- QK: A2-pair-outer; finish 4 nb blocks, fold max, pack fp16 ----
        float rm0 = -1e30f, rm1 = -1e30f;
        unsigned spg[16], spg8[16];
#pragma unroll
        for (int ap = 0; ap < 4; ap++) {
            float s[4][4];
            unsigned ring[3][4];
            ldsm4(ring[0][0], ring[0][1], ring[0][2], ring[0][3],
                  kb2 + colK[0] + (unsigned)((2 * ap) * 2048));
            ldsm4(ring[1][0], ring[1][1], ring[1][2], ring[1][3],
                  kb2 + colK[0] + (unsigned)((2 * ap + 1) * 2048));
#pragma unroll
            for (int st = 0; st < 8; st++) {
                const int kk = st >> 1, hf = st & 1;
                if (st < 6) {
                    const int kk2 = (st + 2) >> 1, h2 = (st + 2) & 1;
                    unsigned* d = ring[(st + 2) % 3];
                    ldsm4(d[0], d[1], d[2], d[3],
                          kb2 + colK[kk2] + (unsigned)((2 * ap + h2) * 2048));
                }
                const unsigned* b = ring[st % 3];
                float* sA = s[2 * hf];
                float* sBv = s[2 * hf + 1];
                if (kk == 0) {
                    const int nbA = 4 * ap + 2 * hf;
                    const float2 bA = *reinterpret_cast<const float2*>(sBb + 8 * nbA + 2 * c);
                    const float2 bB = *reinterpret_cast<const float2*>(sBb + 8 * nbA + 8 + 2 * c);
                    mma16816_init(sA[0], sA[1], sA[2], sA[3],
                                  qf[0][0], qf[0][1], qf[0][2], qf[0][3], b[0], b[1],
                                  bA.x, bA.y);
                    mma16816_init(sBv[0], sBv[1], sBv[2], sBv[3],
                                  qf[0][0], qf[0][1], qf[0][2], qf[0][3], b[2], b[3],
                                  bB.x, bB.y);
                } else {
                    mma16816(sA[0], sA[1], sA[2], sA[3],
                             qf[kk][0], qf[kk][1], qf[kk][2], qf[kk][3], b[0], b[1]);
                    mma16816(sBv[0], sBv[1], sBv[2], sBv[3],
                             qf[kk][0], qf[kk][1], qf[kk][2], qf[kk][3], b[2], b[3]);
                }
            }
#pragma unroll
            for (int u = 0; u < 4; u++) {
                rm0 = fmaxf(rm0, fmaxf(s[u][0], s[u][1]));
                rm1 = fmaxf(rm1, fmaxf(s[u][2], s[u][3]));
                const __half2 h0 = __floats2half2_rn(s[u][0], s[u][1]);
                const __half2 h1 = __floats2half2_rn(s[u][2], s[u][3]);
                spg[4 * ap + u]  = *reinterpret_cast<const unsigned*>(&h0);
                spg8[4 * ap + u] = *reinterpret_cast<const unsigned*>(&h1);
            }
        }

        // ---- softmax stats ----
        rm0 = fmaxf(rm0, __shfl_xor_sync(0xffffffffu, rm0, 1));
        rm0 = fmaxf(rm0, __shfl_xor_sync(0xffffffffu, rm0, 2));
        rm1 = fmaxf(rm1, __shfl_xor_sync(0xffffffffu, rm1, 1));
        rm1 = fmaxf(rm1, __shfl_xor_sync(0xffffffffu, rm1, 2));
        const float mn0 = fmaxf(m0, rm0), mn1 = fmaxf(m1, rm1);
        const float co0 = ex2(m0 - mn0), co1 = ex2(m1 - mn1);
        const bool moved = (mn0 > m0) | (mn1 > m1);
        m0 = mn0; m1 = mn1;
        if (__ballot_sync(0xffffffffu, moved)) {
#pragma unroll
            for (int nb = 0; nb < 8; nb++) {
                acc[nb][0] *= co0; acc[nb][1] *= co0;
                acc[nb][2] *= co1; acc[nb][3] *= co1;
            }
            accl[0] *= co0; accl[1] *= co0;
            accl[2] *= co1; accl[3] *= co1;
        }
        const __half2 mh0 = __floats2half2_rn(mn0, mn0);
        const __half2 mh1 = __floats2half2_rn(mn1, mn1);

        // ---- V ready; PV on single buffer ----
        asm volatile("cp.async.wait_group 1;");   // V(kt) done (K(kt+1) may fly)
        __syncthreads();
        {
            const unsigned ONES = 0x3C003C00u;
            unsigned ring[3][4];
            ldsm4t(ring[0][0], ring[0][1], ring[0][2], ring[0][3], vb2 + colV[0]);
            ldsm4t(ring[1][0], ring[1][1], ring[1][2], ring[1][3], vb2 + colV[1]);
#pragma unroll
            for (int kk = 0; kk < 8; kk++) {
                const unsigned a0 = ex2h(__hsub2(u2h(spg[2 * kk]), mh0));
                const unsigned a1 = ex2h(__hsub2(u2h(spg8[2 * kk]), mh1));
                const unsigned a2 = ex2h(__hsub2(u2h(spg[2 * kk + 1]), mh0));
                const unsigned a3 = ex2h(__hsub2(u2h(spg8[2 * kk + 1]), mh1));
#pragma unroll
                for (int A2 = 0; A2 < 4; A2++) {
                    const int idx = kk * 4 + A2;
                    if (idx + 2 < 32) {
                        const int pkk = (idx + 2) >> 2, pA2 = (idx + 2) & 3;
                        unsigned* d = ring[(idx + 2) % 3];
                        ldsm4t(d[0], d[1], d[2], d[3],
                               vb2 + (unsigned)(pkk * 2048) + colV[pA2]);
                    }
                    const unsigned* b = ring[idx % 3];
                    mma16816(acc[2*A2][0], acc[2*A2][1], acc[2*A2][2], acc[2*A2][3],
                             a0, a1, a2, a3, b[0], b[1]);
                    mma16816(acc[2*A2+1][0], acc[2*A2+1][1], acc[2*A2+1][2], acc[2*A2+1][3],
                             a0, a1, a2, a3, b[2], b[3]);
                }
                mma16816(accl[0], accl[1], accl[2], accl[3],
                         a0, a1, a2, a3, ONES, ONES);
            }
        }
        __syncthreads();   // all warps done reading V before overwrite
        load_V(sb, Vg + (size_t)(kt + 1) * KT * PD, tid, (kt + 2 == nkt) ? lastnch : 8);
        stage ^= 1;
    }

    // ======================= final tile (masked; half for even q_tile) =====
    asm volatile("cp.async.wait_group 1;");   // K(last)
    __syncthreads();
    {
        const unsigned kb2 = sb + (stage ? SK1 : SK0) + (unsigned)kr * 128u;
        const float* sBb = (const float*)(sm + (stage ? SB1 : SB0));
        const int kk0 = grow0 - (nkt - 1) * KT;

#define FINAL_TILE(NA2)                                                          \
        {                                                                        \
            float rm0 = -1e30f, rm1 = -1e30f;                                    \
            unsigned spg[2 * NA2], spg8[2 * NA2];                                \
            _Pragma("unroll")                                                    \
            for (int ap = 0; ap < NA2 / 2; ap++) {                               \
                float s[4][4];                                                   \
                _Pragma("unroll")                                                \
                for (int st = 0; st < 8; st++) {                                 \
                    const int kk = st >> 1, hf = st & 1;                         \
                    unsigned b0, b1, b2, b3;                                     \
                    ldsm4(b0, b1, b2, b3,                                        \
                          kb2 + colK[kk] + (unsigned)((2 * ap + hf) * 2048));    \
                    float* sA = s[2 * hf];                                       \
                    float* sBv = s[2 * hf + 1];                                  \
                    if (kk == 0) {                                               \
                        const int nbA = 4 * ap + 2 * hf;                         \
                        const float2 bA = *reinterpret_cast<const float2*>(      \
                            sBb + 8 * nbA + 2 * c);                              \
                        const float2 bB = *reinterpret_cast<const float2*>(      \
                            sBb + 8 * nbA + 8 + 2 * c);                          \
                        mma16816_init(sA[0], sA[1], sA[2], sA[3],                \
                                      qf[0][0], qf[0][1], qf[0][2], qf[0][3],    \
                                      b0, b1, bA.x, bA.y);                       \
                        mma16816_init(sBv[0], sBv[1], sBv[2], sBv[3],            \
                                      qf[0][0], qf[0][1], qf[0][2], qf[0][3],    \
                                      b2, b3, bB.x, bB.y);                       \
                    } else {                                                     \
                        mma16816(sA[0], sA[1], sA[2], sA[3],                     \
                                 qf[kk][0], qf[kk][1], qf[kk][2], qf[kk][3],     \
                                 b0, b1);                                        \
                        mma16816(sBv[0], sBv[1], sBv[2], sBv[3],                 \
                                 qf[kk][0], qf[kk][1], qf[kk][2], qf[kk][3],     \
                                 b2, b3);                                        \
                    }                                                            \
                }                                                                \
                _Pragma("unroll")                                                \
                for (int u = 0; u < 4; u++) {                                    \
                    const int nb = 4 * ap + u;                                   \
                    const int j0 = 8 * nb + 2 * c, j1 = j0 + 1;                  \
                    if (j0 > kk0)     s[u][0] = -1e30f;                          \
                    if (j1 > kk0)     s[u][1] = -1e30f;                          \
                    if (j0 > kk0 + 8) s[u][2] = -1e30f;                          \
                    if (j1 > kk0 + 8) s[u][3] = -1e30f;                          \
                    rm0 = fmaxf(rm0, fmaxf(s[u][0], s[u][1]));                   \
                    rm1 = fmaxf(rm1, fmaxf(s[u][2], s[u][3]));                   \
                    const __half2 h0 = __floats2half2_rn(s[u][0], s[u][1]);      \
                    const __half2 h1 = __floats2half2_rn(s[u][2], s[u][3]);      \
                    spg[nb]  = *reinterpret_cast<const unsigned*>(&h0);          \
                    spg8[nb] = *reinterpret_cast<const unsigned*>(&h1);          \
                }                                                                \
            }                                                                    \
            rm0 = fmaxf(rm0, __shfl_xor_sync(0xffffffffu, rm0, 1));              \
            rm0 = fmaxf(rm0, __shfl_xor_sync(0xffffffffu, rm0, 2));              \
            rm1 = fmaxf(rm1, __shfl_xor_sync(0xffffffffu, rm1, 1));              \
            rm1 = fmaxf(rm1, __shfl_xor_sync(0xffffffffu, rm1, 2));              \
            const float mn0 = fmaxf(m0, rm0), mn1 = fmaxf(m1, rm1);              \
            const float co0 = ex2(m0 - mn0), co1 = ex2(m1 - mn1);                \
            _Pragma("unroll")                                                    \
            for (int nb = 0; nb < 8; nb++) {                                     \
                acc[nb][0] *= co0; acc[nb][1] *= co0;                            \
                acc[nb][2] *= co1; acc[nb][3] *= co1;                            \
            }                                                                    \
            accl[0] *= co0; accl[1] *= co0;                                      \
            accl[2] *= co1; accl[3] *= co1;                                      \
            const __half2 mh0 = __floats2half2_rn(mn0, mn0);                     \
            const __half2 mh1 = __floats2half2_rn(mn1, mn1);                     \
            asm volatile("cp.async.wait_group 0;");                              \
            __syncthreads();                                                     \
            const unsigned ONES = 0x3C003C00u;                                   \
            _Pragma("unroll")                                                    \
            for (int kk = 0; kk < NA2; kk++) {                                   \
                const unsigned a0 = ex2h(__hsub2(u2h(spg[2 * kk]), mh0));        \
                const unsigned a1 = ex2h(__hsub2(u2h(spg8[2 * kk]), mh1));       \
                const unsigned a2 = ex2h(__hsub2(u2h(spg[2 * kk + 1]), mh0));    \
                const unsigned a3 = ex2h(__hsub2(u2h(spg8[2 * kk + 1]), mh1));   \
                _Pragma("unroll")                                                \
                for (int A2 = 0; A2 < 4; A2++) {                                 \
                    unsigned b0, b1, b2, b3;                                     \
                    ldsm4t(b0, b1, b2, b3,                                       \
                           vb2 + (unsigned)(kk * 2048) + colV[A2]);              \
                    mma16816(acc[2*A2][0], acc[2*A2][1], acc[2*A2][2],           \
                             acc[2*A2][3], a0, a1, a2, a3, b0, b1);              \
                    mma16816(acc[2*A2+1][0], acc[2*A2+1][1], acc[2*A2+1][2],     \
                             acc[2*A2+1][3], a0, a1, a2, a3, b2, b3);            \
                }                                                                \
                mma16816(accl[0], accl[1], accl[2], accl[3],                     \
                         a0, a1, a2, a3, ONES, ONES);                            \
            }                                                                    \
        }

        if (q_tile & 1) FINAL_TILE(8) else FINAL_TILE(4)
#undef FINAL_TILE
    }

    // ---- normalize + write ----
    const float inv0 = 1.0f / accl[0], inv1 = 1.0f / accl[2];
    float* og = out + base + ((size_t)q_tile * QT + 16 * w) * PD;
#pragma unroll
    for (int nb = 0; nb < 8; nb++) {
        *reinterpret_cast<float2*>(og + g * 64 + 8 * nb + 2 * c) =
            make_float2(acc[nb][0] * inv0, acc[nb][1] * inv0);
        *reinterpret_cast<float2*>(og + (g + 8) * 64 + 8 * nb + 2 * c) =
            make_float2(acc[nb][2] * inv1, acc[nb][3] * inv1);
    }
}

// ---------------------------------------------------------------------------
extern "C" void kernel_launch(void* const* d_in, const int* in_sizes, int n_in,
                              void* d_out, int out_size)
{
    const float* Q      = (const float*)d_in[0];
    const float* K      = (const float*)d_in[1];
    const float* V      = (const float*)d_in[2];
    const float* d_bias = (const float*)d_in[3];
    const float* W      = (const float*)d_in[4];
    const float* w_std  = (const float*)d_in[5];
    const float* w_rec  = (const float*)d_in[6];
    const float* w_disc = (const float*)d_in[7];
    float* out = (float*)d_out;

    cudaFuncSetAttribute(attn_kernel, cudaFuncAttributeMaxDynamicSharedMemorySize,
                         SMEM_BYTES);

    dim3 ag(PT / 64, PBH);
    aug_kernel<<<ag, 256>>>(Q, K, V, d_bias, W, w_std, w_rec, w_disc);

    dim3 grid(PT / QT, PBH);
    attn_kernel<<<grid, 128, SMEM_BYTES>>>(out);
}

// round 14
// speedup vs baseline: 1.0521x; 1.0521x over previous
#include <cuda_runtime.h>
#include <cuda_fp16.h>
#include <cstdint>

#define PB 2
#define PH 12
#define PT 2048
#define PD 64
#define PR 16
#define PD_STD 48
#define PBH (PB * PH)
#define QT 64
#define KT 128
#define LOG2E 1.4426950408889634f

// smem byte offsets (attn) — R12 layout, 3 CTA/SM
#define SQ  0
#define SK0 8192
#define SK1 24576
#define SV0 40960
#define SV1 57344
#define SB0 73728
#define SB1 74240
#define SMEM_BYTES 74752

__device__ __half g_Qh[PBH * PT * PD];
__device__ __half g_Kh[PBH * PT * PD];
__device__ __half g_Vh[PBH * PT * PD];
__device__ float  g_bw[PBH * PT];

__device__ __forceinline__ void mma16816(float& d0, float& d1, float& d2, float& d3,
                                         unsigned a0, unsigned a1, unsigned a2, unsigned a3,
                                         unsigned b0, unsigned b1) {
    asm volatile(
        "mma.sync.aligned.m16n8k16.row.col.f32.f16.f16.f32 "
        "{%0,%1,%2,%3},{%4,%5,%6,%7},{%8,%9},{%0,%1,%2,%3};"
        : "+f"(d0), "+f"(d1), "+f"(d2), "+f"(d3)
        : "r"(a0), "r"(a1), "r"(a2), "r"(a3), "r"(b0), "r"(b1));
}
__device__ __forceinline__ void mma16816_init(float& d0, float& d1, float& d2, float& d3,
                                              unsigned a0, unsigned a1, unsigned a2, unsigned a3,
                                              unsigned b0, unsigned b1, float c0, float c1) {
    asm volatile(
        "mma.sync.aligned.m16n8k16.row.col.f32.f16.f16.f32 "
        "{%0,%1,%2,%3},{%4,%5,%6,%7},{%8,%9},{%10,%11,%10,%11};"
        : "=f"(d0), "=f"(d1), "=f"(d2), "=f"(d3)
        : "r"(a0), "r"(a1), "r"(a2), "r"(a3), "r"(b0), "r"(b1),
          "f"(c0), "f"(c1));
}
__device__ __forceinline__ void ldsm4(unsigned& r0, unsigned& r1, unsigned& r2, unsigned& r3,
                                      unsigned addr) {
    asm volatile("ldmatrix.sync.aligned.m8n8.x4.shared.b16 {%0,%1,%2,%3}, [%4];"
                 : "=r"(r0), "=r"(r1), "=r"(r2), "=r"(r3) : "r"(addr));
}
__device__ __forceinline__ void ldsm4t(unsigned& r0, unsigned& r1, unsigned& r2, unsigned& r3,
                                       unsigned addr) {
    asm volatile("ldmatrix.sync.aligned.m8n8.x4.trans.shared.b16 {%0,%1,%2,%3}, [%4];"
                 : "=r"(r0), "=r"(r1), "=r"(r2), "=r"(r3) : "r"(addr));
}
__device__ __forceinline__ void cpa16(unsigned dst, const void* src) {
    asm volatile("cp.async.cg.shared.global [%0], [%1], 16;" :: "r"(dst), "l"(src));
}
__device__ __forceinline__ float ex2(float x) {
    float y; asm("ex2.approx.ftz.f32 %0, %1;" : "=f"(y) : "f"(x)); return y;
}
__device__ __forceinline__ unsigned ex2h(__half2 x) {
    unsigned y;
    asm("ex2.approx.f16x2 %0, %1;" : "=r"(y) : "r"(*reinterpret_cast<const unsigned*>(&x)));
    return y;
}
__device__ __forceinline__ __half2 u2h(unsigned u) {
    return *reinterpret_cast<const __half2*>(&u);
}
__device__ __forceinline__ unsigned h2u(__half2 h) {
    return *reinterpret_cast<const unsigned*>(&h);
}

// ---------------------------------------------------------------------------
// Fused prologue (R12, unchanged): fp16 staging + HFMA2 low-rank projection.
// ---------------------------------------------------------------------------
#define QPH 68
#define WPH 66
__global__ __launch_bounds__(256) void aug_kernel(
    const float* __restrict__ Q, const float* __restrict__ K,
    const float* __restrict__ V, const float* __restrict__ d_bias,
    const float* __restrict__ W,
    const float* __restrict__ w_std, const float* __restrict__ w_rec,
    const float* __restrict__ w_disc)
{
    __shared__ __half sWh[PR * WPH];
    __shared__ __half sQh[64 * QPH];
    __shared__ __half sKh[64 * QPH];
    __shared__ float sLQ[64 * 16];
    __shared__ float sLK[64 * 16];

    const int tid = threadIdx.x;
    const int bh  = blockIdx.y;
    const int h   = bh % PH;
    const int t0  = blockIdx.x * 64;
    const size_t gbase = ((size_t)bh * PT + t0) * PD;

    for (int idx = tid; idx < PD * PR; idx += 256) {
        const int rj = idx & 15, j = idx >> 4;
        sWh[rj * WPH + j] = __float2half_rn(W[j * PR + rj]);
    }
#pragma unroll
    for (int k = 0; k < 4; k++) {
        const int i = tid + k * 256;
        const int r = i >> 4, c4 = (i & 15) * 4;
        const float4 qv = reinterpret_cast<const float4*>(Q + gbase)[i];
        const float4 kv = reinterpret_cast<const float4*>(K + gbase)[i];
        __half2 qh[2] = {__floats2half2_rn(qv.x, qv.y), __floats2half2_rn(qv.z, qv.w)};
        __half2 kh[2] = {__floats2half2_rn(kv.x, kv.y), __floats2half2_rn(kv.z, kv.w)};
        *reinterpret_cast<uint2*>(&sQh[r * QPH + c4]) = *reinterpret_cast<uint2*>(qh);
        *reinterpret_cast<uint2*>(&sKh[r * QPH + c4]) = *reinterpret_cast<uint2*>(kh);
    }
    __syncthreads();

    {
        const int r = tid >> 2, c4 = (tid & 3) * 4;
        __half2 aq[4], ak[4];
#pragma unroll
        for (int u = 0; u < 4; u++) { aq[u] = __half2(0, 0); ak[u] = __half2(0, 0); }
#pragma unroll
        for (int jp = 0; jp < 32; jp++) {
            const __half2 q2 = *reinterpret_cast<const __half2*>(&sQh[r * QPH + 2 * jp]);
            const __half2 k2 = *reinterpret_cast<const __half2*>(&sKh[r * QPH + 2 * jp]);
#pragma unroll
            for (int u = 0; u < 4; u++) {
                const __half2 w2 =
                    *reinterpret_cast<const __half2*>(&sWh[(c4 + u) * WPH + 2 * jp]);
                aq[u] = __hfma2(q2, w2, aq[u]);
                ak[u] = __hfma2(k2, w2, ak[u]);
            }
        }
#pragma unroll
        for (int u = 0; u < 4; u++) {
            sLQ[r * 16 + c4 + u] = __low2float(aq[u]) + __high2float(aq[u]);
            sLK[r * 16 + c4 + u] = __low2float(ak[u]) + __high2float(ak[u]);
        }
    }
    __syncthreads();

    {
        const float sstd = sqrtf(w_std[h]);
        const float srec = sqrtf(w_rec[h]);
        const float SCL = 0.125f * LOG2E;
        const int r = tid >> 2, d0 = (tid & 3) * 16;
        const size_t grow = gbase + (size_t)r * PD + d0;

        __half2 qo[8], ko[8], vo[8];
#pragma unroll
        for (int j = 0; j < 8; j++) {
            const int d = d0 + 2 * j;
            float q0, q1, k0, k1;
            if (d < PD_STD) {
                const __half2 qh = *reinterpret_cast<const __half2*>(&sQh[r * QPH + d]);
                const __half2 kh = *reinterpret_cast<const __half2*>(&sKh[r * QPH + d]);
                q0 = SCL * sstd * __low2float(qh);  q1 = SCL * sstd * __high2float(qh);
                k0 = sstd * __low2float(kh);        k1 = sstd * __high2float(kh);
            } else {
                const int rr = d - PD_STD;
                q0 = SCL * srec * sLK[r * 16 + rr]; q1 = SCL * srec * sLK[r * 16 + rr + 1];
                k0 = srec * sLQ[r * 16 + rr];       k1 = srec * sLQ[r * 16 + rr + 1];
            }
            qo[j] = __floats2half2_rn(q0, q1);
            ko[j] = __floats2half2_rn(k0, k1);
        }
#pragma unroll
        for (int j4 = 0; j4 < 4; j4++) {
            const float4 vv = *reinterpret_cast<const float4*>(&V[grow + 4 * j4]);
            vo[2 * j4]     = __floats2half2_rn(vv.x, vv.y);
            vo[2 * j4 + 1] = __floats2half2_rn(vv.z, vv.w);
        }
        *reinterpret_cast<uint4*>(&g_Qh[grow])     = *reinterpret_cast<uint4*>(&qo[0]);
        *reinterpret_cast<uint4*>(&g_Qh[grow + 8]) = *reinterpret_cast<uint4*>(&qo[4]);
        *reinterpret_cast<uint4*>(&g_Kh[grow])     = *reinterpret_cast<uint4*>(&ko[0]);
        *reinterpret_cast<uint4*>(&g_Kh[grow + 8]) = *reinterpret_cast<uint4*>(&ko[4]);
        *reinterpret_cast<uint4*>(&g_Vh[grow])     = *reinterpret_cast<uint4*>(&vo[0]);
        *reinterpret_cast<uint4*>(&g_Vh[grow + 8]) = *reinterpret_cast<uint4*>(&vo[4]);
        if (tid < 64)
            g_bw[(size_t)bh * PT + t0 + tid] =
                LOG2E * w_disc[h] * d_bias[(size_t)bh * PT + t0 + tid];
    }
}

// ---------------------------------------------------------------------------
// K+V+bias stage loader (R12): one group, double-buffered; nch chunks.
// ---------------------------------------------------------------------------
__device__ __forceinline__ void load_stage(unsigned sb, int stage,
                                           const __half* Kt, const __half* Vt,
                                           const float* bt, int tid, int nch)
{
    const unsigned kb = sb + (stage ? SK1 : SK0);
    const unsigned vb = sb + (stage ? SV1 : SV0);
    const unsigned bb = sb + (stage ? SB1 : SB0);
#pragma unroll
    for (int i = 0; i < 8; i++) {
        if (i < nch) {
            const int ch = tid + i * 128;
            const int r = ch >> 3, a = ch & 7;
            const unsigned off = (unsigned)(r * 128 + ((a ^ (r & 7)) << 4));
            cpa16(kb + off, Kt + r * 64 + a * 8);
            cpa16(vb + off, Vt + r * 64 + a * 8);
        }
    }
    if (tid < 32) cpa16(bb + (unsigned)tid * 16u, bt + tid * 4);
    asm volatile("cp.async.commit_group;");
}

// ---------------------------------------------------------------------------
// Flash attention: R12 skeleton (3 CTA/SM, double-buffered K+V) with
// packed-fp16 S, hmax2 tree max, 2-shuffle packed reduction, HSUB2+ex2.f16x2
// in PV, bias in mma C, ones-column sums, half-tile final epilogue.
// ---------------------------------------------------------------------------
__global__ __launch_bounds__(128, 3) void attn_kernel(float* __restrict__ out)
{
    extern __shared__ char sm[];
    const unsigned sb = (unsigned)__cvta_generic_to_shared(sm);

    const int bh = blockIdx.y;
    const int q_tile = (PT / QT - 1) - blockIdx.x;
    const int nkt = q_tile / 2 + 1;
    const int lastnch = (q_tile & 1) ? 8 : 4;
    const size_t base = (size_t)bh * PT * PD;
    const __half* Kg = g_Kh + base;
    const __half* Vg = g_Vh + base;
    const float*  bg = g_bw + (size_t)bh * PT;

    const int tid = threadIdx.x;
    const int w = tid >> 5, lane = tid & 31;
    const int g = lane >> 2, c = lane & 3;

    const int kr  = 8 * (lane >> 4) + (lane & 7);
    const int kao = (lane >> 3) & 1;
    const int qr  = 16 * w + 8 * ((lane >> 3) & 1) + (lane & 7);
    const int qao = lane >> 4;
    const int vro = 8 * ((lane >> 3) & 1) + (lane & 7);
    const int vao = lane >> 4;
    const int qsw = qr & 7, ksw = kr & 7, vsw = vro & 7;
    const int grow0 = q_tile * QT + 16 * w + g;

    unsigned colK[4], colQ[4], colV[4];
#pragma unroll
    for (int kk = 0; kk < 4; kk++) {
        colK[kk] = (unsigned)(((2 * kk + kao) ^ ksw) << 4);
        colQ[kk] = (unsigned)(((2 * kk + qao) ^ qsw) << 4);
        colV[kk] = (unsigned)(((2 * kk + vao) ^ vsw) << 4);
    }
    const unsigned qbase2 = sb + SQ + (unsigned)qr * 128u;

    load_stage(sb, 0, Kg, Vg, bg, tid, (nkt == 1) ? lastnch : 8);
    {
        const __half* Qt = g_Qh + base + (size_t)q_tile * QT * PD;
#pragma unroll
        for (int i = 0; i < 4; i++) {
            const int ch = tid + i * 128;
            const int r = ch >> 3, a = ch & 7;
            cpa16(sb + SQ + (unsigned)(r * 128 + ((a ^ (r & 7)) << 4)), Qt + r * 64 + a * 8);
        }
        asm volatile("cp.async.commit_group;");
    }
    asm volatile("cp.async.wait_group 0;");
    __syncthreads();

    unsigned qf[4][4];
#pragma unroll
    for (int kk = 0; kk < 4; kk++)
        ldsm4(qf[kk][0], qf[kk][1], qf[kk][2], qf[kk][3], qbase2 + colQ[kk]);

    float acc[8][4];
#pragma unroll
    for (int nb = 0; nb < 8; nb++)
#pragma unroll
        for (int j = 0; j < 4; j++) acc[nb][j] = 0.f;
    float accl[4] = {0.f, 0.f, 0.f, 0.f};
    __half2 mold2 = __float2half2_rn(-60000.f);   // running (m_row_g, m_row_g8)

    int stage = 0;
    // ======================= main loop: full, unmasked tiles ================
    for (int kt = 0; kt < nkt - 1; kt++) {
        if (kt) {
            asm volatile("cp.async.wait_group 0;");
            __syncthreads();
        }
        load_stage(sb, stage ^ 1, Kg + (size_t)(kt + 1) * KT * PD,
                   Vg + (size_t)(kt + 1) * KT * PD, bg + (kt + 1) * KT, tid,
                   (kt + 2 == nkt) ? lastnch : 8);

        const unsigned kb2 = sb + (stage ? SK1 : SK0) + (unsigned)kr * 128u;
        const unsigned vb2 = sb + (stage ? SV1 : SV0) + (unsigned)vro * 128u;
        const float* sBb = (const float*)(sm + (stage ? SB1 : SB0));

        // ---- QK ap-outer; pack to fp16 + fold packed max per 4-nb group ----
        unsigned spg[16], spg8[16];
        __half2 hmA = __float2half2_rn(-60000.f), hmB = hmA;
#pragma unroll
        for (int ap = 0; ap < 4; ap++) {
            float s[4][4];
            unsigned ring[3][4];
            ldsm4(ring[0][0], ring[0][1], ring[0][2], ring[0][3],
                  kb2 + colK[0] + (unsigned)((2 * ap) * 2048));
            ldsm4(ring[1][0], ring[1][1], ring[1][2], ring[1][3],
                  kb2 + colK[0] + (unsigned)((2 * ap + 1) * 2048));
#pragma unroll
            for (int st = 0; st < 8; st++) {
                const int kk = st >> 1, hf = st & 1;
                if (st < 6) {
                    const int kk2 = (st + 2) >> 1, h2 = (st + 2) & 1;
                    unsigned* d = ring[(st + 2) % 3];
                    ldsm4(d[0], d[1], d[2], d[3],
                          kb2 + colK[kk2] + (unsigned)((2 * ap + h2) * 2048));
                }
                const unsigned* b = ring[st % 3];
                float* sA = s[2 * hf];
                float* sBv = s[2 * hf + 1];
                if (kk == 0) {
                    const int nbA = 4 * ap + 2 * hf;
                    const float2 bA = *reinterpret_cast<const float2*>(sBb + 8 * nbA + 2 * c);
                    const float2 bB = *reinterpret_cast<const float2*>(sBb + 8 * nbA + 8 + 2 * c);
                    mma16816_init(sA[0], sA[1], sA[2], sA[3],
                                  qf[0][0], qf[0][1], qf[0][2], qf[0][3], b[0], b[1],
                                  bA.x, bA.y);
                    mma16816_init(sBv[0], sBv[1], sBv[2], sBv[3],
                                  qf[0][0], qf[0][1], qf[0][2], qf[0][3], b[2], b[3],
                                  bB.x, bB.y);
                } else {
                    mma16816(sA[0], sA[1], sA[2], sA[3],
                             qf[kk][0], qf[kk][1], qf[kk][2], qf[kk][3], b[0], b[1]);
                    mma16816(sBv[0], sBv[1], sBv[2], sBv[3],
                             qf[kk][0], qf[kk][1], qf[kk][2], qf[kk][3], b[2], b[3]);
                }
            }
#pragma unroll
            for (int u = 0; u < 4; u++) {
                const __half2 h0 = __floats2half2_rn(s[u][0], s[u][1]);
                const __half2 h1 = __floats2half2_rn(s[u][2], s[u][3]);
                hmA = __hmax2(hmA, h0);
                hmB = __hmax2(hmB, h1);
                spg[4 * ap + u]  = h2u(h0);
                spg8[4 * ap + u] = h2u(h1);
            }
        }

        // ---- packed max reduction: horizontal + 2 cross-lane shuffles ----
        unsigned rmu = h2u(__halves2half2(__hmax(__low2half(hmA), __high2half(hmA)),
                                          __hmax(__low2half(hmB), __high2half(hmB))));
        rmu = h2u(__hmax2(u2h(rmu), u2h(__shfl_xor_sync(0xffffffffu, rmu, 1))));
        rmu = h2u(__hmax2(u2h(rmu), u2h(__shfl_xor_sync(0xffffffffu, rmu, 2))));
        const __half2 mn2 = __hmax2(mold2, u2h(rmu));
        const bool moved = (h2u(mn2) != h2u(mold2));
        const float co0 = ex2(__half2float(__low2half(mold2)) - __half2float(__low2half(mn2)));
        const float co1 = ex2(__half2float(__high2half(mold2)) - __half2float(__high2half(mn2)));
        mold2 = mn2;
        if (__ballot_sync(0xffffffffu, moved)) {
#pragma unroll
            for (int nb = 0; nb < 8; nb++) {
                acc[nb][0] *= co0; acc[nb][1] *= co0;
                acc[nb][2] *= co1; acc[nb][3] *= co1;
            }
            accl[0] *= co0; accl[1] *= co0;
            accl[2] *= co1; accl[3] *= co1;
        }
        const __half2 mh0 = __half2half2(__low2half(mn2));
        const __half2 mh1 = __half2half2(__high2half(mn2));

        // ---- PV: packed exp (HSUB2 + ex2.f16x2), distance-2 V ring ----
        {
            const unsigned ONES = 0x3C003C00u;
            unsigned ring[3][4];
            ldsm4t(ring[0][0], ring[0][1], ring[0][2], ring[0][3], vb2 + colV[0]);
            ldsm4t(ring[1][0], ring[1][1], ring[1][2], ring[1][3], vb2 + colV[1]);
#pragma unroll
            for (int kk = 0; kk < 8; kk++) {
                const unsigned a0 = ex2h(__hsub2(u2h(spg[2 * kk]), mh0));
                const unsigned a1 = ex2h(__hsub2(u2h(spg8[2 * kk]), mh1));
                const unsigned a2 = ex2h(__hsub2(u2h(spg[2 * kk + 1]), mh0));
                const unsigned a3 = ex2h(__hsub2(u2h(spg8[2 * kk + 1]), mh1));
#pragma unroll
                for (int A2 = 0; A2 < 4; A2++) {
                    const int idx = kk * 4 + A2;
                    if (idx + 2 < 32) {
                        const int pkk = (idx + 2) >> 2, pA2 = (idx + 2) & 3;
                        unsigned* d = ring[(idx + 2) % 3];
                        ldsm4t(d[0], d[1], d[2], d[3],
                               vb2 + (unsigned)(pkk * 2048) + colV[pA2]);
                    }
                    const unsigned* b = ring[idx % 3];
                    mma16816(acc[2*A2][0], acc[2*A2][1], acc[2*A2][2], acc[2*A2][3],
                             a0, a1, a2, a3, b[0], b[1]);
                    mma16816(acc[2*A2+1][0], acc[2*A2+1][1], acc[2*A2+1][2], acc[2*A2+1][3],
                             a0, a1, a2, a3, b[2], b[3]);
                }
                mma16816(accl[0], accl[1], accl[2], accl[3],
                         a0, a1, a2, a3, ONES, ONES);
            }
        }
        stage ^= 1;
    }

    // ======================= final tile (masked; half for even q_tile) =====
    if (nkt > 1) {
        asm volatile("cp.async.wait_group 0;");
        __syncthreads();
    }
    {
        const unsigned kb2 = sb + (stage ? SK1 : SK0) + (unsigned)kr * 128u;
        const unsigned vb2 = sb + (stage ? SV1 : SV0) + (unsigned)vro * 128u;
        const float* sBb = (const float*)(sm + (stage ? SB1 : SB0));
        const int kk0 = grow0 - (nkt - 1) * KT;
        const float m0 = __half2float(__low2half(mold2));
        const float m1 = __half2float(__high2half(mold2));

#define FINAL_TILE(NA2)                                                          \
        {                                                                        \
            float rm0 = -1e30f, rm1 = -1e30f;                                    \
            unsigned spg[2 * NA2], spg8[2 * NA2];                                \
            _Pragma("unroll")                                                    \
            for (int ap = 0; ap < NA2 / 2; ap++) {                               \
                float s[4][4];                                                   \
                _Pragma("unroll")                                                \
                for (int st = 0; st < 8; st++) {                                 \
                    const int kk = st >> 1, hf = st & 1;                         \
                    unsigned b0, b1, b2, b3;                                     \
                    ldsm4(b0, b1, b2, b3,                                        \
                          kb2 + colK[kk] + (unsigned)((2 * ap + hf) * 2048));    \
                    float* sA = s[2 * hf];                                       \
                    float* sBv = s[2 * hf + 1];                                  \
                    if (kk == 0) {                                               \
                        const int nbA = 4 * ap + 2 * hf;                         \
                        const float2 bA = *reinterpret_cast<const float2*>(      \
                            sBb + 8 * nbA + 2 * c);                              \
                        const float2 bB = *reinterpret_cast<const float2*>(      \
                            sBb + 8 * nbA + 8 + 2 * c);                          \
                        mma16816_init(sA[0], sA[1], sA[2], sA[3],                \
                                      qf[0][0], qf[0][1], qf[0][2], qf[0][3],    \
                                      b0, b1, bA.x, bA.y);                       \
                        mma16816_init(sBv[0], sBv[1], sBv[2], sBv[3],            \
                                      qf[0][0], qf[0][1], qf[0][2], qf[0][3],    \
                                      b2, b3, bB.x, bB.y);                       \
                    } else {                                                     \
                        mma16816(sA[0], sA[1], sA[2], sA[3],                     \
                                 qf[kk][0], qf[kk][1], qf[kk][2], qf[kk][3],     \
                                 b0, b1);                                        \
                        mma16816(sBv[0], sBv[1], sBv[2], sBv[3],                 \
                                 qf[kk][0], qf[kk][1], qf[kk][2], qf[kk][3],     \
                                 b2, b3);                                        \
                    }                                                            \
                }                                                                \
                _Pragma("unroll")                                                \
                for (int u = 0; u < 4; u++) {                                    \
                    const int nb = 4 * ap + u;                                   \
                    const int j0 = 8 * nb + 2 * c, j1 = j0 + 1;                  \
                    if (j0 > kk0)     s[u][0] = -1e30f;                          \
                    if (j1 > kk0)     s[u][1] = -1e30f;                          \
                    if (j0 > kk0 + 8) s[u][2] = -1e30f;                          \
                    if (j1 > kk0 + 8) s[u][3] = -1e30f;                          \
                    rm0 = fmaxf(rm0, fmaxf(s[u][0], s[u][1]));                   \
                    rm1 = fmaxf(rm1, fmaxf(s[u][2], s[u][3]));                   \
                    const __half2 h0 = __floats2half2_rn(s[u][0], s[u][1]);      \
                    const __half2 h1 = __floats2half2_rn(s[u][2], s[u][3]);      \
                    spg[nb]  = h2u(h0);                                          \
                    spg8[nb] = h2u(h1);                                          \
                }                                                                \
            }                                                                    \
            rm0 = fmaxf(rm0, __shfl_xor_sync(0xffffffffu, rm0, 1));              \
            rm0 = fmaxf(rm0, __shfl_xor_sync(0xffffffffu, rm0, 2));              \
            rm1 = fmaxf(rm1, __shfl_xor_sync(0xffffffffu, rm1, 1));              \
            rm1 = fmaxf(rm1, __shfl_xor_sync(0xffffffffu, rm1, 2));              \
            const __half hn0 = __float2half_rn(fmaxf(m0, rm0));                  \
            const __half hn1 = __float2half_rn(fmaxf(m1, rm1));                  \
            const float mn0 = __half2float(hn0), mn1 = __half2float(hn1);        \
            const float co0 = ex2(m0 - mn0), co1 = ex2(m1 - mn1);                \
            _Pragma("unroll")                                                    \
            for (int nb = 0; nb < 8; nb++) {                                     \
                acc[nb][0] *= co0; acc[nb][1] *= co0;                            \
                acc[nb][2] *= co1; acc[nb][3] *= co1;                            \
            }                                                                    \
            accl[0] *= co0; accl[1] *= co0;                                      \
            accl[2] *= co1; accl[3] *= co1;                                      \
            const __half2 mh0 = __half2half2(hn0);                               \
            const __half2 mh1 = __half2half2(hn1);                               \
            const unsigned ONES = 0x3C003C00u;                                   \
            _Pragma("unroll")                                                    \
            for (int kk = 0; kk < NA2; kk++) {                                   \
                const unsigned a0 = ex2h(__hsub2(u2h(spg[2 * kk]), mh0));        \
                const unsigned a1 = ex2h(__hsub2(u2h(spg8[2 * kk]), mh1));       \
                const unsigned a2 = ex2h(__hsub2(u2h(spg[2 * kk + 1]), mh0));    \
                const unsigned a3 = ex2h(__hsub2(u2h(spg8[2 * kk + 1]), mh1));   \
                _Pragma("unroll")                                                \
                for (int A2 = 0; A2 < 4; A2++) {                                 \
                    unsigned b0, b1, b2, b3;                                     \
                    ldsm4t(b0, b1, b2, b3,                                       \
                           vb2 + (unsigned)(kk * 2048) + colV[A2]);              \
                    mma16816(acc[2*A2][0], acc[2*A2][1], acc[2*A2][2],           \
                             acc[2*A2][3], a0, a1, a2, a3, b0, b1);              \
                    mma16816(acc[2*A2+1][0], acc[2*A2+1][1], acc[2*A2+1][2],     \
                             acc[2*A2+1][3], a0, a1, a2, a3, b2, b3);            \
                }                                                                \
                mma16816(accl[0], accl[1], accl[2], accl[3],                     \
                         a0, a1, a2, a3, ONES, ONES);                            \
            }                                                                    \
        }

        if (q_tile & 1) FINAL_TILE(8) else FINAL_TILE(4)
#undef FINAL_TILE
    }

    // ---- normalize + write ----
    const float inv0 = 1.0f / accl[0], inv1 = 1.0f / accl[2];
    float* og = out + base + ((size_t)q_tile * QT + 16 * w) * PD;
#pragma unroll
    for (int nb = 0; nb < 8; nb++) {
        *reinterpret_cast<float2*>(og + g * 64 + 8 * nb + 2 * c) =
            make_float2(acc[nb][0] * inv0, acc[nb][1] * inv0);
        *reinterpret_cast<float2*>(og + (g + 8) * 64 + 8 * nb + 2 * c) =
            make_float2(acc[nb][2] * inv1, acc[nb][3] * inv1);
    }
}

// ---------------------------------------------------------------------------
extern "C" void kernel_launch(void* const* d_in, const int* in_sizes, int n_in,
                              void* d_out, int out_size)
{
    const float* Q      = (const float*)d_in[0];
    const float* K      = (const float*)d_in[1];
    const float* V      = (const float*)d_in[2];
    const float* d_bias = (const float*)d_in[3];
    const float* W      = (const float*)d_in[4];
    const float* w_std  = (const float*)d_in[5];
    const float* w_rec  = (const float*)d_in[6];
    const float* w_disc = (const float*)d_in[7];
    float* out = (float*)d_out;

    cudaFuncSetAttribute(attn_kernel, cudaFuncAttributeMaxDynamicSharedMemorySize,
                         SMEM_BYTES);

    dim3 ag(PT / 64, PBH);
    aug_kernel<<<ag, 256>>>(Q, K, V, d_bias, W, w_std, w_rec, w_disc);

    dim3 grid(PT / QT, PBH);
    attn_kernel<<<grid, 128, SMEM_BYTES>>>(out);
}

// round 15
// speedup vs baseline: 1.0619x; 1.0094x over previous
#include <cuda_runtime.h>
#include <cuda_fp16.h>
#include <cstdint>

#define PB 2
#define PH 12
#define PT 2048
#define PD 64
#define PR 16
#define PD_STD 48
#define PBH (PB * PH)
#define QT 64
#define KT 128
#define LOG2E 1.4426950408889634f

// smem byte offsets (attn) — 3 CTA/SM
#define SQ  0
#define SK0 8192
#define SK1 24576
#define SV0 40960
#define SV1 57344
#define SB0 73728
#define SB1 74240
#define SMEM_BYTES 74752

__device__ __half g_Qh[PBH * PT * PD];
__device__ __half g_Kh[PBH * PT * PD];
__device__ __half g_Vh[PBH * PT * PD];
__device__ float  g_bw[PBH * PT];

__device__ __forceinline__ void mma16816(float& d0, float& d1, float& d2, float& d3,
                                         unsigned a0, unsigned a1, unsigned a2, unsigned a3,
                                         unsigned b0, unsigned b1) {
    asm volatile(
        "mma.sync.aligned.m16n8k16.row.col.f32.f16.f16.f32 "
        "{%0,%1,%2,%3},{%4,%5,%6,%7},{%8,%9},{%0,%1,%2,%3};"
        : "+f"(d0), "+f"(d1), "+f"(d2), "+f"(d3)
        : "r"(a0), "r"(a1), "r"(a2), "r"(a3), "r"(b0), "r"(b1));
}
__device__ __forceinline__ void mma16816_init(float& d0, float& d1, float& d2, float& d3,
                                              unsigned a0, unsigned a1, unsigned a2, unsigned a3,
                                              unsigned b0, unsigned b1, float c0, float c1) {
    asm volatile(
        "mma.sync.aligned.m16n8k16.row.col.f32.f16.f16.f32 "
        "{%0,%1,%2,%3},{%4,%5,%6,%7},{%8,%9},{%10,%11,%10,%11};"
        : "=f"(d0), "=f"(d1), "=f"(d2), "=f"(d3)
        : "r"(a0), "r"(a1), "r"(a2), "r"(a3), "r"(b0), "r"(b1),
          "f"(c0), "f"(c1));
}
__device__ __forceinline__ void ldsm4(unsigned& r0, unsigned& r1, unsigned& r2, unsigned& r3,
                                      unsigned addr) {
    asm volatile("ldmatrix.sync.aligned.m8n8.x4.shared.b16 {%0,%1,%2,%3}, [%4];"
                 : "=r"(r0), "=r"(r1), "=r"(r2), "=r"(r3) : "r"(addr));
}
__device__ __forceinline__ void ldsm4t(unsigned& r0, unsigned& r1, unsigned& r2, unsigned& r3,
                                       unsigned addr) {
    asm volatile("ldmatrix.sync.aligned.m8n8.x4.trans.shared.b16 {%0,%1,%2,%3}, [%4];"
                 : "=r"(r0), "=r"(r1), "=r"(r2), "=r"(r3) : "r"(addr));
}
__device__ __forceinline__ void cpa16(unsigned dst, const void* src) {
    asm volatile("cp.async.cg.shared.global [%0], [%1], 16;" :: "r"(dst), "l"(src));
}
__device__ __forceinline__ float ex2(float x) {
    float y; asm("ex2.approx.ftz.f32 %0, %1;" : "=f"(y) : "f"(x)); return y;
}
__device__ __forceinline__ unsigned ex2h(__half2 x) {
    unsigned y;
    asm("ex2.approx.f16x2 %0, %1;" : "=r"(y) : "r"(*reinterpret_cast<const unsigned*>(&x)));
    return y;
}
__device__ __forceinline__ __half2 u2h(unsigned u) {
    return *reinterpret_cast<const __half2*>(&u);
}
__device__ __forceinline__ unsigned h2u(__half2 h) {
    return *reinterpret_cast<const unsigned*>(&h);
}

// ---------------------------------------------------------------------------
// Fused prologue (unchanged): fp16 staging + HFMA2 low-rank projection.
// ---------------------------------------------------------------------------
#define QPH 68
#define WPH 66
__global__ __launch_bounds__(256) void aug_kernel(
    const float* __restrict__ Q, const float* __restrict__ K,
    const float* __restrict__ V, const float* __restrict__ d_bias,
    const float* __restrict__ W,
    const float* __restrict__ w_std, const float* __restrict__ w_rec,
    const float* __restrict__ w_disc)
{
    __shared__ __half sWh[PR * WPH];
    __shared__ __half sQh[64 * QPH];
    __shared__ __half sKh[64 * QPH];
    __shared__ float sLQ[64 * 16];
    __shared__ float sLK[64 * 16];

    const int tid = threadIdx.x;
    const int bh  = blockIdx.y;
    const int h   = bh % PH;
    const int t0  = blockIdx.x * 64;
    const size_t gbase = ((size_t)bh * PT + t0) * PD;

    for (int idx = tid; idx < PD * PR; idx += 256) {
        const int rj = idx & 15, j = idx >> 4;
        sWh[rj * WPH + j] = __float2half_rn(W[j * PR + rj]);
    }
#pragma unroll
    for (int k = 0; k < 4; k++) {
        const int i = tid + k * 256;
        const int r = i >> 4, c4 = (i & 15) * 4;
        const float4 qv = reinterpret_cast<const float4*>(Q + gbase)[i];
        const float4 kv = reinterpret_cast<const float4*>(K + gbase)[i];
        __half2 qh[2] = {__floats2half2_rn(qv.x, qv.y), __floats2half2_rn(qv.z, qv.w)};
        __half2 kh[2] = {__floats2half2_rn(kv.x, kv.y), __floats2half2_rn(kv.z, kv.w)};
        *reinterpret_cast<uint2*>(&sQh[r * QPH + c4]) = *reinterpret_cast<uint2*>(qh);
        *reinterpret_cast<uint2*>(&sKh[r * QPH + c4]) = *reinterpret_cast<uint2*>(kh);
    }
    __syncthreads();

    {
        const int r = tid >> 2, c4 = (tid & 3) * 4;
        __half2 aq[4], ak[4];
#pragma unroll
        for (int u = 0; u < 4; u++) { aq[u] = __half2(0, 0); ak[u] = __half2(0, 0); }
#pragma unroll
        for (int jp = 0; jp < 32; jp++) {
            const __half2 q2 = *reinterpret_cast<const __half2*>(&sQh[r * QPH + 2 * jp]);
            const __half2 k2 = *reinterpret_cast<const __half2*>(&sKh[r * QPH + 2 * jp]);
#pragma unroll
            for (int u = 0; u < 4; u++) {
                const __half2 w2 =
                    *reinterpret_cast<const __half2*>(&sWh[(c4 + u) * WPH + 2 * jp]);
                aq[u] = __hfma2(q2, w2, aq[u]);
                ak[u] = __hfma2(k2, w2, ak[u]);
            }
        }
#pragma unroll
        for (int u = 0; u < 4; u++) {
            sLQ[r * 16 + c4 + u] = __low2float(aq[u]) + __high2float(aq[u]);
            sLK[r * 16 + c4 + u] = __low2float(ak[u]) + __high2float(ak[u]);
        }
    }
    __syncthreads();

    {
        const float sstd = sqrtf(w_std[h]);
        const float srec = sqrtf(w_rec[h]);
        const float SCL = 0.125f * LOG2E;
        const int r = tid >> 2, d0 = (tid & 3) * 16;
        const size_t grow = gbase + (size_t)r * PD + d0;

        __half2 qo[8], ko[8], vo[8];
#pragma unroll
        for (int j = 0; j < 8; j++) {
            const int d = d0 + 2 * j;
            float q0, q1, k0, k1;
            if (d < PD_STD) {
                const __half2 qh = *reinterpret_cast<const __half2*>(&sQh[r * QPH + d]);
                const __half2 kh = *reinterpret_cast<const __half2*>(&sKh[r * QPH + d]);
                q0 = SCL * sstd * __low2float(qh);  q1 = SCL * sstd * __high2float(qh);
                k0 = sstd * __low2float(kh);        k1 = sstd * __high2float(kh);
            } else {
                const int rr = d - PD_STD;
                q0 = SCL * srec * sLK[r * 16 + rr]; q1 = SCL * srec * sLK[r * 16 + rr + 1];
                k0 = srec * sLQ[r * 16 + rr];       k1 = srec * sLQ[r * 16 + rr + 1];
            }
            qo[j] = __floats2half2_rn(q0, q1);
            ko[j] = __floats2half2_rn(k0, k1);
        }
#pragma unroll
        for (int j4 = 0; j4 < 4; j4++) {
            const float4 vv = *reinterpret_cast<const float4*>(&V[grow + 4 * j4]);
            vo[2 * j4]     = __floats2half2_rn(vv.x, vv.y);
            vo[2 * j4 + 1] = __floats2half2_rn(vv.z, vv.w);
        }
        *reinterpret_cast<uint4*>(&g_Qh[grow])     = *reinterpret_cast<uint4*>(&qo[0]);
        *reinterpret_cast<uint4*>(&g_Qh[grow + 8]) = *reinterpret_cast<uint4*>(&qo[4]);
        *reinterpret_cast<uint4*>(&g_Kh[grow])     = *reinterpret_cast<uint4*>(&ko[0]);
        *reinterpret_cast<uint4*>(&g_Kh[grow + 8]) = *reinterpret_cast<uint4*>(&ko[4]);
        *reinterpret_cast<uint4*>(&g_Vh[grow])     = *reinterpret_cast<uint4*>(&vo[0]);
        *reinterpret_cast<uint4*>(&g_Vh[grow + 8]) = *reinterpret_cast<uint4*>(&vo[4]);
        if (tid < 64)
            g_bw[(size_t)bh * PT + t0 + tid] =
                LOG2E * w_disc[h] * d_bias[(size_t)bh * PT + t0 + tid];
    }
}

// ---------------------------------------------------------------------------
// K+V+bias stage loader: one group, double-buffered; nch chunks.
// ---------------------------------------------------------------------------
__device__ __forceinline__ void load_stage(unsigned sb, int stage,
                                           const __half* Kt, const __half* Vt,
                                           const float* bt, int tid, int nch)
{
    const unsigned kb = sb + (stage ? SK1 : SK0);
    const unsigned vb = sb + (stage ? SV1 : SV0);
    const unsigned bb = sb + (stage ? SB1 : SB0);
#pragma unroll
    for (int i = 0; i < 8; i++) {
        if (i < nch) {
            const int ch = tid + i * 128;
            const int r = ch >> 3, a = ch & 7;
            const unsigned off = (unsigned)(r * 128 + ((a ^ (r & 7)) << 4));
            cpa16(kb + off, Kt + r * 64 + a * 8);
            cpa16(vb + off, Vt + r * 64 + a * 8);
        }
    }
    if (tid < 32) cpa16(bb + (unsigned)tid * 16u, bt + tid * 4);
    asm volatile("cp.async.commit_group;");
}

// ---------------------------------------------------------------------------
// Flash attention: R14 + upfront-8 K-fragment prefetch per ap-group and
// full-kk-ahead V prefetch (vbuf parity) with exp one kk ahead (af parity).
// ---------------------------------------------------------------------------
__global__ __launch_bounds__(128, 3) void attn_kernel(float* __restrict__ out)
{
    extern __shared__ char sm[];
    const unsigned sb = (unsigned)__cvta_generic_to_shared(sm);

    const int bh = blockIdx.y;
    const int q_tile = (PT / QT - 1) - blockIdx.x;
    const int nkt = q_tile / 2 + 1;
    const int lastnch = (q_tile & 1) ? 8 : 4;
    const size_t base = (size_t)bh * PT * PD;
    const __half* Kg = g_Kh + base;
    const __half* Vg = g_Vh + base;
    const float*  bg = g_bw + (size_t)bh * PT;

    const int tid = threadIdx.x;
    const int w = tid >> 5, lane = tid & 31;
    const int g = lane >> 2, c = lane & 3;

    const int kr  = 8 * (lane >> 4) + (lane & 7);
    const int kao = (lane >> 3) & 1;
    const int qr  = 16 * w + 8 * ((lane >> 3) & 1) + (lane & 7);
    const int qao = lane >> 4;
    const int vro = 8 * ((lane >> 3) & 1) + (lane & 7);
    const int vao = lane >> 4;
    const int qsw = qr & 7, ksw = kr & 7, vsw = vro & 7;
    const int grow0 = q_tile * QT + 16 * w + g;

    unsigned colK[4], colQ[4], colV[4];
#pragma unroll
    for (int kk = 0; kk < 4; kk++) {
        colK[kk] = (unsigned)(((2 * kk + kao) ^ ksw) << 4);
        colQ[kk] = (unsigned)(((2 * kk + qao) ^ qsw) << 4);
        colV[kk] = (unsigned)(((2 * kk + vao) ^ vsw) << 4);
    }
    const unsigned qbase2 = sb + SQ + (unsigned)qr * 128u;

    load_stage(sb, 0, Kg, Vg, bg, tid, (nkt == 1) ? lastnch : 8);
    {
        const __half* Qt = g_Qh + base + (size_t)q_tile * QT * PD;
#pragma unroll
        for (int i = 0; i < 4; i++) {
            const int ch = tid + i * 128;
            const int r = ch >> 3, a = ch & 7;
            cpa16(sb + SQ + (unsigned)(r * 128 + ((a ^ (r & 7)) << 4)), Qt + r * 64 + a * 8);
        }
        asm volatile("cp.async.commit_group;");
    }
    asm volatile("cp.async.wait_group 0;");
    __syncthreads();

    unsigned qf[4][4];
#pragma unroll
    for (int kk = 0; kk < 4; kk++)
        ldsm4(qf[kk][0], qf[kk][1], qf[kk][2], qf[kk][3], qbase2 + colQ[kk]);

    float acc[8][4];
#pragma unroll
    for (int nb = 0; nb < 8; nb++)
#pragma unroll
        for (int j = 0; j < 4; j++) acc[nb][j] = 0.f;
    float accl[4] = {0.f, 0.f, 0.f, 0.f};
    __half2 mold2 = __float2half2_rn(-60000.f);

    int stage = 0;
    // ======================= main loop: full, unmasked tiles ================
    for (int kt = 0; kt < nkt - 1; kt++) {
        if (kt) {
            asm volatile("cp.async.wait_group 0;");
            __syncthreads();
        }
        load_stage(sb, stage ^ 1, Kg + (size_t)(kt + 1) * KT * PD,
                   Vg + (size_t)(kt + 1) * KT * PD, bg + (kt + 1) * KT, tid,
                   (kt + 2 == nkt) ? lastnch : 8);

        const unsigned kb2 = sb + (stage ? SK1 : SK0) + (unsigned)kr * 128u;
        const unsigned vb2 = sb + (stage ? SV1 : SV0) + (unsigned)vro * 128u;
        const float* sBb = (const float*)(sm + (stage ? SB1 : SB0));

        // ---- QK ap-outer; ALL 8 K fragments prefetched up front ----
        unsigned spg[16], spg8[16];
        __half2 hmA = __float2half2_rn(-60000.f), hmB = hmA;
#pragma unroll
        for (int ap = 0; ap < 4; ap++) {
            unsigned kbuf[8][4];
#pragma unroll
            for (int st = 0; st < 8; st++) {
                const int kk = st >> 1, hf = st & 1;
                ldsm4(kbuf[st][0], kbuf[st][1], kbuf[st][2], kbuf[st][3],
                      kb2 + colK[kk] + (unsigned)((2 * ap + hf) * 2048));
            }
            float s[4][4];
#pragma unroll
            for (int st = 0; st < 8; st++) {
                const int kk = st >> 1, hf = st & 1;
                const unsigned* b = kbuf[st];
                float* sA = s[2 * hf];
                float* sBv = s[2 * hf + 1];
                if (kk == 0) {
                    const int nbA = 4 * ap + 2 * hf;
                    const float2 bA = *reinterpret_cast<const float2*>(sBb + 8 * nbA + 2 * c);
                    const float2 bB = *reinterpret_cast<const float2*>(sBb + 8 * nbA + 8 + 2 * c);
                    mma16816_init(sA[0], sA[1], sA[2], sA[3],
                                  qf[0][0], qf[0][1], qf[0][2], qf[0][3], b[0], b[1],
                                  bA.x, bA.y);
                    mma16816_init(sBv[0], sBv[1], sBv[2], sBv[3],
                                  qf[0][0], qf[0][1], qf[0][2], qf[0][3], b[2], b[3],
                                  bB.x, bB.y);
                } else {
                    mma16816(sA[0], sA[1], sA[2], sA[3],
                             qf[kk][0], qf[kk][1], qf[kk][2], qf[kk][3], b[0], b[1]);
                    mma16816(sBv[0], sBv[1], sBv[2], sBv[3],
                             qf[kk][0], qf[kk][1], qf[kk][2], qf[kk][3], b[2], b[3]);
                }
            }
#pragma unroll
            for (int u = 0; u < 4; u++) {
                const __half2 h0 = __floats2half2_rn(s[u][0], s[u][1]);
                const __half2 h1 = __floats2half2_rn(s[u][2], s[u][3]);
                hmA = __hmax2(hmA, h0);
                hmB = __hmax2(hmB, h1);
                spg[4 * ap + u]  = h2u(h0);
                spg8[4 * ap + u] = h2u(h1);
            }
        }

        // ---- packed max reduction ----
        unsigned rmu = h2u(__halves2half2(__hmax(__low2half(hmA), __high2half(hmA)),
                                          __hmax(__low2half(hmB), __high2half(hmB))));
        rmu = h2u(__hmax2(u2h(rmu), u2h(__shfl_xor_sync(0xffffffffu, rmu, 1))));
        rmu = h2u(__hmax2(u2h(rmu), u2h(__shfl_xor_sync(0xffffffffu, rmu, 2))));
        const __half2 mn2 = __hmax2(mold2, u2h(rmu));
        const bool moved = (h2u(mn2) != h2u(mold2));
        const float co0 = ex2(__half2float(__low2half(mold2)) - __half2float(__low2half(mn2)));
        const float co1 = ex2(__half2float(__high2half(mold2)) - __half2float(__high2half(mn2)));
        mold2 = mn2;
        if (__ballot_sync(0xffffffffu, moved)) {
#pragma unroll
            for (int nb = 0; nb < 8; nb++) {
                acc[nb][0] *= co0; acc[nb][1] *= co0;
                acc[nb][2] *= co1; acc[nb][3] *= co1;
            }
            accl[0] *= co0; accl[1] *= co0;
            accl[2] *= co1; accl[3] *= co1;
        }
        const __half2 mh0 = __half2half2(__low2half(mn2));
        const __half2 mh1 = __half2half2(__high2half(mn2));

        // ---- PV: full-kk-ahead V prefetch + exp one kk ahead ----
        {
            const unsigned ONES = 0x3C003C00u;
            unsigned vbuf[2][4][4];
            unsigned af[2][4];
#pragma unroll
            for (int A2 = 0; A2 < 4; A2++)
                ldsm4t(vbuf[0][A2][0], vbuf[0][A2][1], vbuf[0][A2][2], vbuf[0][A2][3],
                       vb2 + colV[A2]);
            af[0][0] = ex2h(__hsub2(u2h(spg[0]), mh0));
            af[0][1] = ex2h(__hsub2(u2h(spg8[0]), mh1));
            af[0][2] = ex2h(__hsub2(u2h(spg[1]), mh0));
            af[0][3] = ex2h(__hsub2(u2h(spg8[1]), mh1));
#pragma unroll
            for (int kk = 0; kk < 8; kk++) {
                if (kk < 7) {
#pragma unroll
                    for (int A2 = 0; A2 < 4; A2++)
                        ldsm4t(vbuf[(kk + 1) & 1][A2][0], vbuf[(kk + 1) & 1][A2][1],
                               vbuf[(kk + 1) & 1][A2][2], vbuf[(kk + 1) & 1][A2][3],
                               vb2 + (unsigned)((kk + 1) * 2048) + colV[A2]);
                    unsigned* an = af[(kk + 1) & 1];
                    an[0] = ex2h(__hsub2(u2h(spg[2 * kk + 2]), mh0));
                    an[1] = ex2h(__hsub2(u2h(spg8[2 * kk + 2]), mh1));
                    an[2] = ex2h(__hsub2(u2h(spg[2 * kk + 3]), mh0));
                    an[3] = ex2h(__hsub2(u2h(spg8[2 * kk + 3]), mh1));
                }
                const unsigned* aa = af[kk & 1];
#pragma unroll
                for (int A2 = 0; A2 < 4; A2++) {
                    const unsigned* b = vbuf[kk & 1][A2];
                    mma16816(acc[2*A2][0], acc[2*A2][1], acc[2*A2][2], acc[2*A2][3],
                             aa[0], aa[1], aa[2], aa[3], b[0], b[1]);
                    mma16816(acc[2*A2+1][0], acc[2*A2+1][1], acc[2*A2+1][2], acc[2*A2+1][3],
                             aa[0], aa[1], aa[2], aa[3], b[2], b[3]);
                }
                mma16816(accl[0], accl[1], accl[2], accl[3],
                         aa[0], aa[1], aa[2], aa[3], ONES, ONES);
            }
        }
        stage ^= 1;
    }

    // ======================= final tile (masked; half for even q_tile) =====
    if (nkt > 1) {
        asm volatile("cp.async.wait_group 0;");
        __syncthreads();
    }
    {
        const unsigned kb2 = sb + (stage ? SK1 : SK0) + (unsigned)kr * 128u;
        const unsigned vb2 = sb + (stage ? SV1 : SV0) + (unsigned)vro * 128u;
        const float* sBb = (const float*)(sm + (stage ? SB1 : SB0));
        const int kk0 = grow0 - (nkt - 1) * KT;
        const float m0 = __half2float(__low2half(mold2));
        const float m1 = __half2float(__high2half(mold2));

#define FINAL_TILE(NA2)                                                          \
        {                                                                        \
            float rm0 = -1e30f, rm1 = -1e30f;                                    \
            unsigned spg[2 * NA2], spg8[2 * NA2];                                \
            _Pragma("unroll")                                                    \
            for (int ap = 0; ap < NA2 / 2; ap++) {                               \
                float s[4][4];                                                   \
                _Pragma("unroll")                                                \
                for (int st = 0; st < 8; st++) {                                 \
                    const int kk = st >> 1, hf = st & 1;                         \
                    unsigned b0, b1, b2, b3;                                     \
                    ldsm4(b0, b1, b2, b3,                                        \
                          kb2 + colK[kk] + (unsigned)((2 * ap + hf) * 2048));    \
                    float* sA = s[2 * hf];                                       \
                    float* sBv = s[2 * hf + 1];                                  \
                    if (kk == 0) {                                               \
                        const int nbA = 4 * ap + 2 * hf;                         \
                        const float2 bA = *reinterpret_cast<const float2*>(      \
                            sBb + 8 * nbA + 2 * c);                              \
                        const float2 bB = *reinterpret_cast<const float2*>(      \
                            sBb + 8 * nbA + 8 + 2 * c);                          \
                        mma16816_init(sA[0], sA[1], sA[2], sA[3],                \
                                      qf[0][0], qf[0][1], qf[0][2], qf[0][3],    \
                                      b0, b1, bA.x, bA.y);                       \
                        mma16816_init(sBv[0], sBv[1], sBv[2], sBv[3],            \
                                      qf[0][0], qf[0][1], qf[0][2], qf[0][3],    \
                                      b2, b3, bB.x, bB.y);                       \
                    } else {                                                     \
                        mma16816(sA[0], sA[1], sA[2], sA[3],                     \
                                 qf[kk][0], qf[kk][1], qf[kk][2], qf[kk][3],     \
                                 b0, b1);                                        \
                        mma16816(sBv[0], sBv[1], sBv[2], sBv[3],                 \
                                 qf[kk][0], qf[kk][1], qf[kk][2], qf[kk][3],     \
                                 b2, b3);                                        \
                    }                                                            \
                }                                                                \
                _Pragma("unroll")                                                \
                for (int u = 0; u < 4; u++) {                                    \
                    const int nb = 4 * ap + u;                                   \
                    const int j0 = 8 * nb + 2 * c, j1 = j0 + 1;                  \
                    if (j0 > kk0)     s[u][0] = -1e30f;                          \
                    if (j1 > kk0)     s[u][1] = -1e30f;                          \
                    if (j0 > kk0 + 8) s[u][2] = -1e30f;                          \
                    if (j1 > kk0 + 8) s[u][3] = -1e30f;                          \
                    rm0 = fmaxf(rm0, fmaxf(s[u][0], s[u][1]));                   \
                    rm1 = fmaxf(rm1, fmaxf(s[u][2], s[u][3]));                   \
                    const __half2 h0 = __floats2half2_rn(s[u][0], s[u][1]);      \
                    const __half2 h1 = __floats2half2_rn(s[u][2], s[u][3]);      \
                    spg[nb]  = h2u(h0);                                          \
                    spg8[nb] = h2u(h1);                                          \
                }                                                                \
            }                                                                    \
            rm0 = fmaxf(rm0, __shfl_xor_sync(0xffffffffu, rm0, 1));              \
            rm0 = fmaxf(rm0, __shfl_xor_sync(0xffffffffu, rm0, 2));              \
            rm1 = fmaxf(rm1, __shfl_xor_sync(0xffffffffu, rm1, 1));              \
            rm1 = fmaxf(rm1, __shfl_xor_sync(0xffffffffu, rm1, 2));              \
            const __half hn0 = __float2half_rn(fmaxf(m0, rm0));                  \
            const __half hn1 = __float2half_rn(fmaxf(m1, rm1));                  \
            const float mn0 = __half2float(hn0), mn1 = __half2float(hn1);        \
            const float co0 = ex2(m0 - mn0), co1 = ex2(m1 - mn1);                \
            _Pragma("unroll")                                                    \
            for (int nb = 0; nb < 8; nb++) {                                     \
                acc[nb][0] *= co0; acc[nb][1] *= co0;                            \
                acc[nb][2] *= co1; acc[nb][3] *= co1;                            \
            }                                                                    \
            accl[0] *= co0; accl[1] *= co0;                                      \
            accl[2] *= co1; accl[3] *= co1;                                      \
            const __half2 mh0 = __half2half2(hn0);                               \
            const __half2 mh1 = __half2half2(hn1);                               \
            const unsigned ONES = 0x3C003C00u;                                   \
            _Pragma("unroll")                                                    \
            for (int kk = 0; kk < NA2; kk++) {                                   \
                const unsigned a0 = ex2h(__hsub2(u2h(spg[2 * kk]), mh0));        \
                const unsigned a1 = ex2h(__hsub2(u2h(spg8[2 * kk]), mh1));       \
                const unsigned a2 = ex2h(__hsub2(u2h(spg[2 * kk + 1]), mh0));    \
                const unsigned a3 = ex2h(__hsub2(u2h(spg8[2 * kk + 1]), mh1));   \
                _Pragma("unroll")                                                \
                for (int A2 = 0; A2 < 4; A2++) {                                 \
                    unsigned b0, b1, b2, b3;                                     \
                    ldsm4t(b0, b1, b2, b3,                                       \
                           vb2 + (unsigned)(kk * 2048) + colV[A2]);              \
                    mma16816(acc[2*A2][0], acc[2*A2][1], acc[2*A2][2],           \
                             acc[2*A2][3], a0, a1, a2, a3, b0, b1);              \
                    mma16816(acc[2*A2+1][0], acc[2*A2+1][1], acc[2*A2+1][2],     \
                             acc[2*A2+1][3], a0, a1, a2, a3, b2, b3);            \
                }                                                                \
                mma16816(accl[0], accl[1], accl[2], accl[3],                     \
                         a0, a1, a2, a3, ONES, ONES);                            \
            }                                                                    \
        }

        if (q_tile & 1) FINAL_TILE(8) else FINAL_TILE(4)
#undef FINAL_TILE
    }

    // ---- normalize + write ----
    const float inv0 = 1.0f / accl[0], inv1 = 1.0f / accl[2];
    float* og = out + base + ((size_t)q_tile * QT + 16 * w) * PD;
#pragma unroll
    for (int nb = 0; nb < 8; nb++) {
        *reinterpret_cast<float2*>(og + g * 64 + 8 * nb + 2 * c) =
            make_float2(acc[nb][0] * inv0, acc[nb][1] * inv0);
        *reinterpret_cast<float2*>(og + (g + 8) * 64 + 8 * nb + 2 * c) =
            make_float2(acc[nb][2] * inv1, acc[nb][3] * inv1);
    }
}

// ---------------------------------------------------------------------------
extern "C" void kernel_launch(void* const* d_in, const int* in_sizes, int n_in,
                              void* d_out, int out_size)
{
    const float* Q      = (const float*)d_in[0];
    const float* K      = (const float*)d_in[1];
    const float* V      = (const float*)d_in[2];
    const float* d_bias = (const float*)d_in[3];
    const float* W      = (const float*)d_in[4];
    const float* w_std  = (const float*)d_in[5];
    const float* w_rec  = (const float*)d_in[6];
    const float* w_disc = (const float*)d_in[7];
    float* out = (float*)d_out;

    cudaFuncSetAttribute(attn_kernel, cudaFuncAttributeMaxDynamicSharedMemorySize,
                         SMEM_BYTES);

    dim3 ag(PT / 64, PBH);
    aug_kernel<<<ag, 256>>>(Q, K, V, d_bias, W, w_std, w_rec, w_disc);

    dim3 grid(PT / QT, PBH);
    attn_kernel<<<grid, 128, SMEM_BYTES>>>(out);
}